// round 3
// baseline (speedup 1.0000x reference)
#include <cuda_runtime.h>
#include <math.h>

#define MAXN 100000
#define MAXE 1600000
#define MAXET (MAXE + MAXN)
#define DH 64
#define NG 128
#define NC 10
#define NEG 0.2f

// ---------------- static device scratch ----------------
__device__ int   g_is64;
__device__ int   g_esrc[MAXE];
__device__ int   g_edst[MAXE];
__device__ int   g_batch[MAXN];
__device__ int   g_deg[MAXN];
__device__ int   g_ptr[MAXN + 1];
__device__ int   g_src[MAXET];
__device__ __align__(16) float g_hA[MAXN * DH];
__device__ __align__(16) float g_hB[MAXN * DH];
__device__ float g_as[MAXN];
__device__ float g_ad[MAXN];
__device__ __align__(16) float g_pool[NG * DH];
__device__ int   g_cnt[NG];
__device__ int   g_part[64];

// ---------------- dtype detection: int64 (odd 32-bit words all zero) vs int32 ----------------
__global__ void k_detect(const unsigned int* __restrict__ w, int E) {
    __shared__ int nz;
    if (threadIdx.x == 0) nz = 0;
    __syncthreads();
    for (int k = threadIdx.x; k < 1024; k += blockDim.x) {
        long long pos = 2ll * ((long long)k * (E - 1) / 1024) + 1;  // odd word, within first 2E words
        if (w[pos] != 0u) atomicAdd(&nz, 1);
    }
    __syncthreads();
    if (threadIdx.x == 0) g_is64 = (nz == 0) ? 1 : 0;
}

// ---------------- convert edge_index / batch to int32 (clamped) ----------------
__global__ void k_convert_edges(const void* __restrict__ ei, int E, int n) {
    int i = blockIdx.x * blockDim.x + threadIdx.x;
    if (i >= E) return;
    int s, d;
    if (g_is64) {
        const long long* p = (const long long*)ei;
        s = (int)p[i];
        d = (int)p[(size_t)E + i];
    } else {
        const int* p = (const int*)ei;
        s = p[i];
        d = p[E + i];
    }
    g_esrc[i] = min(max(s, 0), n - 1);
    g_edst[i] = min(max(d, 0), n - 1);
}

__global__ void k_convert_batch(const void* __restrict__ b, int n) {
    int i = blockIdx.x * blockDim.x + threadIdx.x;
    if (i >= n) return;
    int v;
    if (g_is64) v = (int)((const long long*)b)[i];
    else        v = ((const int*)b)[i];
    g_batch[i] = min(max(v, 0), NG - 1);
}

// ---------------- init ----------------
__global__ void k_init(int n) {
    int i = blockIdx.x * blockDim.x + threadIdx.x;
    if (i < n) g_deg[i] = 1;              // self loop pre-counted
    if (i < NG * DH) g_pool[i] = 0.f;
    if (i < NG) g_cnt[i] = 0;
}

// ---------------- degree count ----------------
__global__ void k_degcount(int E) {
    int i = blockIdx.x * blockDim.x + threadIdx.x;
    if (i < E) atomicAdd(&g_deg[g_edst[i]], 1);
}

// ---------------- 3-kernel exclusive scan: g_deg -> g_ptr ----------------
__global__ void k_scan1(int n) {
    __shared__ int sh[256];
    int base = blockIdx.x * 2048 + threadIdx.x * 8;
    int s = 0;
#pragma unroll
    for (int k = 0; k < 8; k++) {
        int idx = base + k;
        if (idx < n) s += g_deg[idx];
    }
    sh[threadIdx.x] = s;
    __syncthreads();
    for (int o = 128; o > 0; o >>= 1) {
        if (threadIdx.x < o) sh[threadIdx.x] += sh[threadIdx.x + o];
        __syncthreads();
    }
    if (threadIdx.x == 0) g_part[blockIdx.x] = sh[0];
}

__global__ void k_scan2(int nb, int n) {
    if (threadIdx.x == 0 && blockIdx.x == 0) {
        int run = 0;
        for (int b = 0; b < nb; b++) {
            int t = g_part[b];
            g_part[b] = run;
            run += t;
        }
        g_ptr[n] = run;
    }
}

__global__ void k_scan3(int n) {
    __shared__ int sh[256];
    int base = blockIdx.x * 2048 + threadIdx.x * 8;
    int loc[8];
    int s = 0;
#pragma unroll
    for (int k = 0; k < 8; k++) {
        int idx = base + k;
        loc[k] = s;
        if (idx < n) s += g_deg[idx];
    }
    sh[threadIdx.x] = s;
    __syncthreads();
    for (int o = 1; o < 256; o <<= 1) {
        int t = 0;
        if ((int)threadIdx.x >= o) t = sh[threadIdx.x - o];
        __syncthreads();
        sh[threadIdx.x] += t;
        __syncthreads();
    }
    int off = g_part[blockIdx.x] + sh[threadIdx.x] - s;  // exclusive
#pragma unroll
    for (int k = 0; k < 8; k++) {
        int idx = base + k;
        if (idx < n) {
            g_ptr[idx] = off + loc[k];
            g_deg[idx] = 0;  // reuse as fill counter
        }
    }
}

// ---------------- scatter edges (+self loops) into CSR ----------------
__global__ void k_scatter(int E, int n) {
    int i = blockIdx.x * blockDim.x + threadIdx.x;
    int tot = E + n;
    if (i >= tot) return;
    int s, d;
    if (i < E) { s = g_esrc[i]; d = g_edst[i]; }
    else       { s = d = i - E; }
    int p = atomicAdd(&g_deg[d], 1);
    g_src[g_ptr[d] + p] = s;
}

// ---------------- node transform, layer 1 (in-dim 3) ----------------
__global__ void k_transform_in(const float* __restrict__ x, const float* __restrict__ pos,
                               const float* __restrict__ W, const float* __restrict__ asrc,
                               const float* __restrict__ adst, int n) {
    __shared__ float ss[8], sd[8];
    int g = threadIdx.x >> 6;
    int c = threadIdx.x & 63;
    int node = blockIdx.x * 4 + g;
    bool valid = node < n;
    float h = 0.f;
    if (valid) {
        float p0 = pos[node * 2];
        float p1 = pos[node * 2 + 1];
        float xv = x[node];
        h = p0 * W[c] + p1 * W[64 + c] + xv * W[128 + c];
        g_hB[(size_t)node * DH + c] = h;
    }
    float vs = valid ? h * asrc[c] : 0.f;
    float vd = valid ? h * adst[c] : 0.f;
#pragma unroll
    for (int o = 16; o > 0; o >>= 1) {
        vs += __shfl_xor_sync(0xffffffffu, vs, o);
        vd += __shfl_xor_sync(0xffffffffu, vd, o);
    }
    int w = threadIdx.x >> 5;
    if ((threadIdx.x & 31) == 0) { ss[w] = vs; sd[w] = vd; }
    __syncthreads();
    if (valid && (threadIdx.x & 63) == 0) {
        g_as[node] = ss[w] + ss[w + 1];
        g_ad[node] = sd[w] + sd[w + 1];
    }
}

// ---------------- node transform, layers 2/3 (in-dim 64): g_hA -> g_hB ----------------
__global__ void k_transform64(const float* __restrict__ W, const float* __restrict__ asrc,
                              const float* __restrict__ adst, int n) {
    __shared__ float s_h[4][DH];
    __shared__ float ss[8], sd[8];
    int g = threadIdx.x >> 6;
    int c = threadIdx.x & 63;
    int node = blockIdx.x * 4 + g;
    bool valid = node < n;
    s_h[g][c] = valid ? g_hA[(size_t)node * DH + c] : 0.f;
    __syncthreads();
    float h = 0.f;
#pragma unroll
    for (int k = 0; k < DH; k++) h += s_h[g][k] * W[k * DH + c];
    if (valid) g_hB[(size_t)node * DH + c] = h;
    float vs = valid ? h * asrc[c] : 0.f;
    float vd = valid ? h * adst[c] : 0.f;
#pragma unroll
    for (int o = 16; o > 0; o >>= 1) {
        vs += __shfl_xor_sync(0xffffffffu, vs, o);
        vd += __shfl_xor_sync(0xffffffffu, vd, o);
    }
    int w = threadIdx.x >> 5;
    if ((threadIdx.x & 31) == 0) { ss[w] = vs; sd[w] = vd; }
    __syncthreads();
    if (valid && (threadIdx.x & 63) == 0) {
        g_as[node] = ss[w] + ss[w + 1];
        g_ad[node] = sd[w] + sd[w + 1];
    }
}

// ---------------- GAT aggregation: one warp per dst node, g_hB -> g_hA ----------------
__device__ __forceinline__ float lrelu(float t) { return t > 0.f ? t : NEG * t; }

__global__ void k_aggregate(const float* __restrict__ bias, int n) {
    int node = blockIdx.x * 8 + (threadIdx.x >> 5);
    if (node >= n) return;
    int lane = threadIdx.x & 31;
    int start = g_ptr[node];
    int end = g_ptr[node + 1];
    int deg = end - start;  // >= 1
    float ad = g_ad[node];
    const float2* h2 = (const float2*)g_hB;
    float2 acc = make_float2(0.f, 0.f);

    if (deg <= 32) {
        int sv = 0;
        float e = -1e30f;
        if (lane < deg) {
            sv = g_src[start + lane];
            e = lrelu(g_as[sv] + ad);
        }
        float m = e;
#pragma unroll
        for (int o = 16; o > 0; o >>= 1) m = fmaxf(m, __shfl_xor_sync(0xffffffffu, m, o));
        float w = (lane < deg) ? __expf(e - m) : 0.f;
        float s = w;
#pragma unroll
        for (int o = 16; o > 0; o >>= 1) s += __shfl_xor_sync(0xffffffffu, s, o);
        w *= 1.f / (s + 1e-16f);
        for (int t = 0; t < deg; t++) {
            int st = __shfl_sync(0xffffffffu, sv, t);
            float wt = __shfl_sync(0xffffffffu, w, t);
            float2 hv = h2[(size_t)st * 32 + lane];  // coalesced 256B row read
            acc.x += wt * hv.x;
            acc.y += wt * hv.y;
        }
    } else {
        float m = -1e30f;
        for (int j = start + lane; j < end; j += 32)
            m = fmaxf(m, lrelu(g_as[g_src[j]] + ad));
#pragma unroll
        for (int o = 16; o > 0; o >>= 1) m = fmaxf(m, __shfl_xor_sync(0xffffffffu, m, o));
        float s = 0.f;
        for (int j = start + lane; j < end; j += 32)
            s += __expf(lrelu(g_as[g_src[j]] + ad) - m);
#pragma unroll
        for (int o = 16; o > 0; o >>= 1) s += __shfl_xor_sync(0xffffffffu, s, o);
        float invs = 1.f / (s + 1e-16f);
        for (int base = start; base < end; base += 32) {
            int cnt = min(32, end - base);
            int sv = 0;
            float w = 0.f;
            if (lane < cnt) {
                sv = g_src[base + lane];
                w = __expf(lrelu(g_as[sv] + ad) - m) * invs;
            }
            for (int t = 0; t < cnt; t++) {
                int st = __shfl_sync(0xffffffffu, sv, t);
                float wt = __shfl_sync(0xffffffffu, w, t);
                float2 hv = h2[(size_t)st * 32 + lane];
                acc.x += wt * hv.x;
                acc.y += wt * hv.y;
            }
        }
    }
    float2 bb = ((const float2*)bias)[lane];
    ((float2*)g_hA)[(size_t)node * 32 + lane] = make_float2(acc.x + bb.x, acc.y + bb.y);
}

// ---------------- pooling (sorted batch, run-length pre-aggregation), reads g_hA ----------------
__global__ void k_pool(int n) {
    int c = threadIdx.x & 63;
    int chunk = blockIdx.x * 4 + (threadIdx.x >> 6);
    int i0 = chunk * 64;
    if (i0 >= n) return;
    int iend = min(i0 + 64, n);
    float acc = 0.f;
    int cacc = 0;
    int cur = g_batch[i0];
    for (int i = i0; i < iend; i++) {
        int b = g_batch[i];
        if (b != cur) {
            atomicAdd(&g_pool[cur * DH + c], acc);
            if (c == 0) atomicAdd(&g_cnt[cur], cacc);
            acc = 0.f; cacc = 0; cur = b;
        }
        acc += g_hA[(size_t)i * DH + c];
        cacc++;
    }
    atomicAdd(&g_pool[cur * DH + c], acc);
    if (c == 0) atomicAdd(&g_cnt[cur], cacc);
}

// ---------------- classifier head ----------------
__global__ void k_final(const float* __restrict__ Wl, const float* __restrict__ bl,
                        float* __restrict__ out) {
    int t = blockIdx.x * blockDim.x + threadIdx.x;
    if (t >= NG * NC) return;
    int g = t / NC;
    int cls = t % NC;
    float invc = 1.f / fmaxf((float)g_cnt[g], 1.f);
    float dot = 0.f;
#pragma unroll
    for (int d = 0; d < DH; d++) dot += g_pool[g * DH + d] * Wl[d * NC + cls];
    out[t] = dot * invc + bl[cls];
}

// ---------------- host launcher ----------------
extern "C" void kernel_launch(void* const* d_in, const int* in_sizes, int n_in,
                              void* d_out, int out_size) {
    const float* x = (const float*)d_in[0];
    const float* pos = (const float*)d_in[1];
    const void* ei = d_in[2];
    const void* batch = d_in[3];
    const float* W1 = (const float*)d_in[4];
    const float* as1 = (const float*)d_in[5];
    const float* ad1 = (const float*)d_in[6];
    const float* b1 = (const float*)d_in[7];
    const float* W2 = (const float*)d_in[8];
    const float* as2 = (const float*)d_in[9];
    const float* ad2 = (const float*)d_in[10];
    const float* b2 = (const float*)d_in[11];
    const float* W3 = (const float*)d_in[12];
    const float* as3 = (const float*)d_in[13];
    const float* ad3 = (const float*)d_in[14];
    const float* b3 = (const float*)d_in[15];
    const float* Wl = (const float*)d_in[16];
    const float* bl = (const float*)d_in[17];
    float* out = (float*)d_out;

    int n = in_sizes[0];
    int E = in_sizes[2] / 2;
    int nb = (n + 2047) / 2048;

    // dtype detect + convert to int32
    k_detect<<<1, 256>>>((const unsigned int*)ei, E);
    k_convert_edges<<<(E + 255) / 256, 256>>>(ei, E, n);
    k_convert_batch<<<(n + 255) / 256, 256>>>(batch, n);

    // init + CSR build
    int initT = n;
    if (initT < NG * DH) initT = NG * DH;
    k_init<<<(initT + 255) / 256, 256>>>(n);
    k_degcount<<<(E + 255) / 256, 256>>>(E);
    k_scan1<<<nb, 256>>>(n);
    k_scan2<<<1, 32>>>(nb, n);
    k_scan3<<<nb, 256>>>(n);
    k_scatter<<<(E + n + 255) / 256, 256>>>(E, n);

    int tb = (n + 3) / 4;
    int ab = (n + 7) / 8;

    // layer 1
    k_transform_in<<<tb, 256>>>(x, pos, W1, as1, ad1, n);
    k_aggregate<<<ab, 256>>>(b1, n);
    // layer 2
    k_transform64<<<tb, 256>>>(W2, as2, ad2, n);
    k_aggregate<<<ab, 256>>>(b2, n);
    // layer 3
    k_transform64<<<tb, 256>>>(W3, as3, ad3, n);
    k_aggregate<<<ab, 256>>>(b3, n);

    // pooling + head
    int chunks = (n + 63) / 64;
    k_pool<<<(chunks + 3) / 4, 256>>>(n);
    k_final<<<(NG * NC + 255) / 256, 256>>>(Wl, bl, out);
}

// round 4
// speedup vs baseline: 1.2044x; 1.2044x over previous
#include <cuda_runtime.h>
#include <math.h>

#define MAXN 100000
#define MAXE 1600000
#define MAXET (MAXE + MAXN)
#define DH 64
#define NG 128
#define NC 10
#define NEG 0.2f
#define TN 16   // nodes per transform tile

// ---------------- static device scratch ----------------
__device__ int   g_is64;
__device__ int   g_esrc[MAXE];
__device__ int   g_edst[MAXE];
__device__ int   g_batch[MAXN];
__device__ int   g_deg[MAXN];
__device__ int   g_ptr[MAXN + 1];
__device__ int   g_src[MAXET];
__device__ __align__(16) float g_hA[MAXN * DH];
__device__ __align__(16) float g_hB[MAXN * DH];
__device__ float g_as[MAXN];
__device__ float g_ad[MAXN];
__device__ __align__(16) float g_pool[NG * DH];
__device__ int   g_cnt[NG];
__device__ int   g_part[64];

// ---------------- dtype detection: int64 (odd 32-bit words all zero) vs int32 ----------------
__global__ void k_detect(const unsigned int* __restrict__ w, int E) {
    __shared__ int nz;
    if (threadIdx.x == 0) nz = 0;
    __syncthreads();
    for (int k = threadIdx.x; k < 1024; k += blockDim.x) {
        long long pos = 2ll * ((long long)k * (E - 1) / 1024) + 1;
        if (w[pos] != 0u) atomicAdd(&nz, 1);
    }
    __syncthreads();
    if (threadIdx.x == 0) g_is64 = (nz == 0) ? 1 : 0;
}

// ---------------- init (before edge conversion: deg pre-counts self loop) ----------------
__global__ void k_init(int n) {
    int i = blockIdx.x * blockDim.x + threadIdx.x;
    if (i < n) g_deg[i] = 1;
    if (i < NG * DH) g_pool[i] = 0.f;
    if (i < NG) g_cnt[i] = 0;
}

// ---------------- convert edges to int32 (clamped) + fused degree count ----------------
__global__ void k_convert_edges(const void* __restrict__ ei, int E, int n) {
    int i = blockIdx.x * blockDim.x + threadIdx.x;
    if (i >= E) return;
    int s, d;
    if (g_is64) {
        const long long* p = (const long long*)ei;
        s = (int)p[i];
        d = (int)p[(size_t)E + i];
    } else {
        const int* p = (const int*)ei;
        s = p[i];
        d = p[E + i];
    }
    s = min(max(s, 0), n - 1);
    d = min(max(d, 0), n - 1);
    g_esrc[i] = s;
    g_edst[i] = d;
    atomicAdd(&g_deg[d], 1);
}

__global__ void k_convert_batch(const void* __restrict__ b, int n) {
    int i = blockIdx.x * blockDim.x + threadIdx.x;
    if (i >= n) return;
    int v;
    if (g_is64) v = (int)((const long long*)b)[i];
    else        v = ((const int*)b)[i];
    g_batch[i] = min(max(v, 0), NG - 1);
}

// ---------------- 3-kernel exclusive scan: g_deg -> g_ptr ----------------
__global__ void k_scan1(int n) {
    __shared__ int sh[256];
    int base = blockIdx.x * 2048 + threadIdx.x * 8;
    int s = 0;
#pragma unroll
    for (int k = 0; k < 8; k++) {
        int idx = base + k;
        if (idx < n) s += g_deg[idx];
    }
    sh[threadIdx.x] = s;
    __syncthreads();
    for (int o = 128; o > 0; o >>= 1) {
        if (threadIdx.x < o) sh[threadIdx.x] += sh[threadIdx.x + o];
        __syncthreads();
    }
    if (threadIdx.x == 0) g_part[blockIdx.x] = sh[0];
}

__global__ void k_scan2(int nb, int n) {
    if (threadIdx.x == 0 && blockIdx.x == 0) {
        int run = 0;
        for (int b = 0; b < nb; b++) {
            int t = g_part[b];
            g_part[b] = run;
            run += t;
        }
        g_ptr[n] = run;
    }
}

__global__ void k_scan3(int n) {
    __shared__ int sh[256];
    int base = blockIdx.x * 2048 + threadIdx.x * 8;
    int loc[8];
    int s = 0;
#pragma unroll
    for (int k = 0; k < 8; k++) {
        int idx = base + k;
        loc[k] = s;
        if (idx < n) s += g_deg[idx];
    }
    sh[threadIdx.x] = s;
    __syncthreads();
    for (int o = 1; o < 256; o <<= 1) {
        int t = 0;
        if ((int)threadIdx.x >= o) t = sh[threadIdx.x - o];
        __syncthreads();
        sh[threadIdx.x] += t;
        __syncthreads();
    }
    int off = g_part[blockIdx.x] + sh[threadIdx.x] - s;
#pragma unroll
    for (int k = 0; k < 8; k++) {
        int idx = base + k;
        if (idx < n) {
            g_ptr[idx] = off + loc[k];
            g_deg[idx] = 0;
        }
    }
}

// ---------------- scatter edges (+self loops) into CSR ----------------
__global__ void k_scatter(int E, int n) {
    int i = blockIdx.x * blockDim.x + threadIdx.x;
    int tot = E + n;
    if (i >= tot) return;
    int s, d;
    if (i < E) { s = g_esrc[i]; d = g_edst[i]; }
    else       { s = d = i - E; }
    int p = atomicAdd(&g_deg[d], 1);
    g_src[g_ptr[d] + p] = s;
}

// ---------------- node transform, layer 1 (in-dim 3) ----------------
__global__ void k_transform_in(const float* __restrict__ x, const float* __restrict__ pos,
                               const float* __restrict__ W, const float* __restrict__ asrc,
                               const float* __restrict__ adst, int n) {
    __shared__ float ss[8], sd[8];
    int g = threadIdx.x >> 6;
    int c = threadIdx.x & 63;
    int node = blockIdx.x * 4 + g;
    bool valid = node < n;
    float h = 0.f;
    if (valid) {
        float p0 = pos[node * 2];
        float p1 = pos[node * 2 + 1];
        float xv = x[node];
        h = p0 * W[c] + p1 * W[64 + c] + xv * W[128 + c];
        g_hB[(size_t)node * DH + c] = h;
    }
    float vs = valid ? h * asrc[c] : 0.f;
    float vd = valid ? h * adst[c] : 0.f;
#pragma unroll
    for (int o = 16; o > 0; o >>= 1) {
        vs += __shfl_xor_sync(0xffffffffu, vs, o);
        vd += __shfl_xor_sync(0xffffffffu, vd, o);
    }
    int w = threadIdx.x >> 5;
    if ((threadIdx.x & 31) == 0) { ss[w] = vs; sd[w] = vd; }
    __syncthreads();
    if (valid && (threadIdx.x & 63) == 0) {
        g_as[node] = ss[w] + ss[w + 1];
        g_ad[node] = sd[w] + sd[w + 1];
    }
}

// ---------------- node transform, layers 2/3: g_hA -> g_hB ----------------
// Persistent grid-stride blocks; W staged in smem once per block (float4, 4 cols/thread).
__global__ __launch_bounds__(256) void k_transform64(const float* __restrict__ W,
                                                     const float* __restrict__ asrc,
                                                     const float* __restrict__ adst,
                                                     int n, int ntiles) {
    __shared__ float4 sW[DH * 16];       // sW[k*16 + c4] = W[k][4c4 .. 4c4+3]
    __shared__ float s_h[TN][DH + 1];    // padded to kill bank conflicts
    int tid = threadIdx.x;
    for (int i = tid; i < DH * 16; i += 256) sW[i] = ((const float4*)W)[i];
    int g = tid >> 4;        // node-in-tile 0..15
    int c4 = tid & 15;       // column quad 0..15
    float4 as4 = ((const float4*)asrc)[c4];
    float4 ad4 = ((const float4*)adst)[c4];
    __syncthreads();

    for (int tile = blockIdx.x; tile < ntiles; tile += gridDim.x) {
        int node = tile * TN + g;
        float4 v = (node < n) ? ((const float4*)g_hA)[(size_t)node * 16 + c4]
                              : make_float4(0.f, 0.f, 0.f, 0.f);
        s_h[g][c4 * 4 + 0] = v.x;
        s_h[g][c4 * 4 + 1] = v.y;
        s_h[g][c4 * 4 + 2] = v.z;
        s_h[g][c4 * 4 + 3] = v.w;
        __syncthreads();
        float4 acc = make_float4(0.f, 0.f, 0.f, 0.f);
#pragma unroll
        for (int k = 0; k < DH; k++) {
            float hk = s_h[g][k];
            float4 w4 = sW[k * 16 + c4];
            acc.x += hk * w4.x;
            acc.y += hk * w4.y;
            acc.z += hk * w4.z;
            acc.w += hk * w4.w;
        }
        if (node < n) ((float4*)g_hB)[(size_t)node * 16 + c4] = acc;
        float vs = acc.x * as4.x + acc.y * as4.y + acc.z * as4.z + acc.w * as4.w;
        float vd = acc.x * ad4.x + acc.y * ad4.y + acc.z * ad4.z + acc.w * ad4.w;
#pragma unroll
        for (int o = 8; o > 0; o >>= 1) {
            vs += __shfl_xor_sync(0xffffffffu, vs, o);
            vd += __shfl_xor_sync(0xffffffffu, vd, o);
        }
        if (node < n && c4 == 0) {
            g_as[node] = vs;
            g_ad[node] = vd;
        }
        __syncthreads();
    }
}

// ---------------- GAT aggregation: warp/node, paired-edge float4 loads ----------------
__device__ __forceinline__ float lrelu(float t) { return t > 0.f ? t : NEG * t; }

__global__ __launch_bounds__(256) void k_aggregate(const float* __restrict__ bias, int n) {
    int node = blockIdx.x * 8 + (threadIdx.x >> 5);
    if (node >= n) return;
    int lane = threadIdx.x & 31;
    int half = lane >> 4;      // 0: even edges, 1: odd edges
    int qc = lane & 15;        // column quad within row
    int start = g_ptr[node];
    int end = g_ptr[node + 1];
    int deg = end - start;     // >= 1
    float ad = g_ad[node];
    const float4* __restrict__ h4 = (const float4*)g_hB;
    float4 acc = make_float4(0.f, 0.f, 0.f, 0.f);

    if (deg <= 32) {
        int sv = 0;
        float e = -1e30f;
        if (lane < deg) {
            sv = g_src[start + lane];
            e = lrelu(g_as[sv] + ad);
        }
        float m = e;
#pragma unroll
        for (int o = 16; o > 0; o >>= 1) m = fmaxf(m, __shfl_xor_sync(0xffffffffu, m, o));
        float w = (lane < deg) ? __expf(e - m) : 0.f;
        float s = w;
#pragma unroll
        for (int o = 16; o > 0; o >>= 1) s += __shfl_xor_sync(0xffffffffu, s, o);
        w *= 1.f / (s + 1e-16f);
        for (int t = 0; t < deg; t += 2) {
            int idx = t + half;
            int st = __shfl_sync(0xffffffffu, sv, idx & 31);
            float wt = __shfl_sync(0xffffffffu, w, idx & 31);
            if (idx >= deg) wt = 0.f;
            float4 hv = h4[(size_t)st * 16 + qc];
            acc.x += wt * hv.x;
            acc.y += wt * hv.y;
            acc.z += wt * hv.z;
            acc.w += wt * hv.w;
        }
    } else {
        float m = -1e30f;
        for (int j = start + lane; j < end; j += 32)
            m = fmaxf(m, lrelu(g_as[g_src[j]] + ad));
#pragma unroll
        for (int o = 16; o > 0; o >>= 1) m = fmaxf(m, __shfl_xor_sync(0xffffffffu, m, o));
        float s = 0.f;
        for (int j = start + lane; j < end; j += 32)
            s += __expf(lrelu(g_as[g_src[j]] + ad) - m);
#pragma unroll
        for (int o = 16; o > 0; o >>= 1) s += __shfl_xor_sync(0xffffffffu, s, o);
        float invs = 1.f / (s + 1e-16f);
        for (int base = start; base < end; base += 32) {
            int cnt = min(32, end - base);
            int sv = 0;
            float w = 0.f;
            if (lane < cnt) {
                sv = g_src[base + lane];
                w = __expf(lrelu(g_as[sv] + ad) - m) * invs;
            }
            for (int t = 0; t < cnt; t += 2) {
                int idx = t + half;
                int st = __shfl_sync(0xffffffffu, sv, idx & 31);
                float wt = __shfl_sync(0xffffffffu, w, idx & 31);
                if (idx >= cnt) wt = 0.f;
                float4 hv = h4[(size_t)st * 16 + qc];
                acc.x += wt * hv.x;
                acc.y += wt * hv.y;
                acc.z += wt * hv.z;
                acc.w += wt * hv.w;
            }
        }
    }
    // combine even/odd halves
    acc.x += __shfl_xor_sync(0xffffffffu, acc.x, 16);
    acc.y += __shfl_xor_sync(0xffffffffu, acc.y, 16);
    acc.z += __shfl_xor_sync(0xffffffffu, acc.z, 16);
    acc.w += __shfl_xor_sync(0xffffffffu, acc.w, 16);
    if (half == 0) {
        float4 bb = ((const float4*)bias)[qc];
        ((float4*)g_hA)[(size_t)node * 16 + qc] =
            make_float4(acc.x + bb.x, acc.y + bb.y, acc.z + bb.z, acc.w + bb.w);
    }
}

// ---------------- pooling (sorted batch, run-length pre-aggregation), reads g_hA ----------------
__global__ void k_pool(int n) {
    int c = threadIdx.x & 63;
    int chunk = blockIdx.x * 4 + (threadIdx.x >> 6);
    int i0 = chunk * 64;
    if (i0 >= n) return;
    int iend = min(i0 + 64, n);
    float acc = 0.f;
    int cacc = 0;
    int cur = g_batch[i0];
    for (int i = i0; i < iend; i++) {
        int b = g_batch[i];
        if (b != cur) {
            atomicAdd(&g_pool[cur * DH + c], acc);
            if (c == 0) atomicAdd(&g_cnt[cur], cacc);
            acc = 0.f; cacc = 0; cur = b;
        }
        acc += g_hA[(size_t)i * DH + c];
        cacc++;
    }
    atomicAdd(&g_pool[cur * DH + c], acc);
    if (c == 0) atomicAdd(&g_cnt[cur], cacc);
}

// ---------------- classifier head ----------------
__global__ void k_final(const float* __restrict__ Wl, const float* __restrict__ bl,
                        float* __restrict__ out) {
    int t = blockIdx.x * blockDim.x + threadIdx.x;
    if (t >= NG * NC) return;
    int g = t / NC;
    int cls = t % NC;
    float invc = 1.f / fmaxf((float)g_cnt[g], 1.f);
    float dot = 0.f;
#pragma unroll
    for (int d = 0; d < DH; d++) dot += g_pool[g * DH + d] * Wl[d * NC + cls];
    out[t] = dot * invc + bl[cls];
}

// ---------------- host launcher ----------------
extern "C" void kernel_launch(void* const* d_in, const int* in_sizes, int n_in,
                              void* d_out, int out_size) {
    const float* x = (const float*)d_in[0];
    const float* pos = (const float*)d_in[1];
    const void* ei = d_in[2];
    const void* batch = d_in[3];
    const float* W1 = (const float*)d_in[4];
    const float* as1 = (const float*)d_in[5];
    const float* ad1 = (const float*)d_in[6];
    const float* b1 = (const float*)d_in[7];
    const float* W2 = (const float*)d_in[8];
    const float* as2 = (const float*)d_in[9];
    const float* ad2 = (const float*)d_in[10];
    const float* b2 = (const float*)d_in[11];
    const float* W3 = (const float*)d_in[12];
    const float* as3 = (const float*)d_in[13];
    const float* ad3 = (const float*)d_in[14];
    const float* b3 = (const float*)d_in[15];
    const float* Wl = (const float*)d_in[16];
    const float* bl = (const float*)d_in[17];
    float* out = (float*)d_out;

    int n = in_sizes[0];
    int E = in_sizes[2] / 2;
    int nb = (n + 2047) / 2048;
    int ntiles = (n + TN - 1) / TN;

    // dtype detect; init; convert+degcount
    k_detect<<<1, 256>>>((const unsigned int*)ei, E);
    int initT = n;
    if (initT < NG * DH) initT = NG * DH;
    k_init<<<(initT + 255) / 256, 256>>>(n);
    k_convert_edges<<<(E + 255) / 256, 256>>>(ei, E, n);
    k_convert_batch<<<(n + 255) / 256, 256>>>(batch, n);

    // CSR build
    k_scan1<<<nb, 256>>>(n);
    k_scan2<<<1, 32>>>(nb, n);
    k_scan3<<<nb, 256>>>(n);
    k_scatter<<<(E + n + 255) / 256, 256>>>(E, n);

    int tb = (n + 3) / 4;
    int ab = (n + 7) / 8;
    int tg = 1184;   // persistent transform blocks (8/SM on 148 SMs)

    // layer 1
    k_transform_in<<<tb, 256>>>(x, pos, W1, as1, ad1, n);
    k_aggregate<<<ab, 256>>>(b1, n);
    // layer 2
    k_transform64<<<tg, 256>>>(W2, as2, ad2, n, ntiles);
    k_aggregate<<<ab, 256>>>(b2, n);
    // layer 3
    k_transform64<<<tg, 256>>>(W3, as3, ad3, n, ntiles);
    k_aggregate<<<ab, 256>>>(b3, n);

    // pooling + head
    int chunks = (n + 63) / 64;
    k_pool<<<(chunks + 3) / 4, 256>>>(n);
    k_final<<<(NG * NC + 255) / 256, 256>>>(Wl, bl, out);
}